// round 1
// baseline (speedup 1.0000x reference)
#include <cuda_runtime.h>
#include <cstdint>

// Problem dims (fixed)
#define Tt 4
#define Ll 2048
#define Bb 8
#define Ee 512
#define Hh 8
#define Dd 64
#define LB (Ll*Bb)        // 16384
#define Mm (Tt*LB)        // 65536
#define N3 (3*Ee)         // 1536

// Scratch (device globals, allocation-free rule)
static __device__ float   g_proj[(size_t)Mm * N3];   // ~402 MB
static __device__ uint8_t g_spk [(size_t)Mm * N3];   // ~100 MB (binary spikes q|k|v)
static __device__ float   g_attn[Tt * 64 * Dd * Dd]; // 4 MB (exact integer counts)
static __device__ float   g_s2  [(size_t)Mm * Ee];   // ~134 MB (final spikes as 0/1 float)

// ---------------------------------------------------------------------------
// Generic fp32 GEMM:  C[m,n] = sum_k A[m,k]*W[n,k] + bias[n]
// A: MxK row-major, W: NxK row-major (both K-contiguous), C: MxN row-major.
// 128x128 block tile, BK=16, 256 threads, 8x8 per thread.
// M,N,K assumed multiples of tile dims (true here).
// ---------------------------------------------------------------------------
__global__ __launch_bounds__(256) void gemm_bias_kernel(
    const float* __restrict__ A, const float* __restrict__ W,
    const float* __restrict__ bias, float* __restrict__ C,
    int M, int N, int K)
{
    const int BM = 128, BN = 128, BK = 16;
    __shared__ float As[BK][BM + 4];
    __shared__ float Ws[BK][BN + 4];

    const int bm = blockIdx.y * BM;
    const int bn = blockIdx.x * BN;
    const int tid = threadIdx.x;
    const int tx = tid & 15;   // 16 cols of threads
    const int ty = tid >> 4;   // 16 rows of threads

    float acc[8][8];
    #pragma unroll
    for (int i = 0; i < 8; i++)
        #pragma unroll
        for (int j = 0; j < 8; j++) acc[i][j] = 0.f;

    for (int k0 = 0; k0 < K; k0 += BK) {
        // Load A tile (BM x BK) -> As[k][m]
        #pragma unroll
        for (int i = tid; i < BM * BK / 4; i += 256) {
            int row = i >> 2, c4 = (i & 3) << 2;
            float4 v = *(const float4*)(A + (size_t)(bm + row) * K + k0 + c4);
            As[c4 + 0][row] = v.x; As[c4 + 1][row] = v.y;
            As[c4 + 2][row] = v.z; As[c4 + 3][row] = v.w;
        }
        // Load W tile (BN x BK) -> Ws[k][n]
        #pragma unroll
        for (int i = tid; i < BN * BK / 4; i += 256) {
            int row = i >> 2, c4 = (i & 3) << 2;
            float4 v = *(const float4*)(W + (size_t)(bn + row) * K + k0 + c4);
            Ws[c4 + 0][row] = v.x; Ws[c4 + 1][row] = v.y;
            Ws[c4 + 2][row] = v.z; Ws[c4 + 3][row] = v.w;
        }
        __syncthreads();

        #pragma unroll
        for (int kk = 0; kk < BK; kk++) {
            float a[8], b[8];
            float4 a0 = *(const float4*)&As[kk][ty * 8];
            float4 a1 = *(const float4*)&As[kk][ty * 8 + 4];
            float4 b0 = *(const float4*)&Ws[kk][tx * 8];
            float4 b1 = *(const float4*)&Ws[kk][tx * 8 + 4];
            a[0]=a0.x;a[1]=a0.y;a[2]=a0.z;a[3]=a0.w;a[4]=a1.x;a[5]=a1.y;a[6]=a1.z;a[7]=a1.w;
            b[0]=b0.x;b[1]=b0.y;b[2]=b0.z;b[3]=b0.w;b[4]=b1.x;b[5]=b1.y;b[6]=b1.z;b[7]=b1.w;
            #pragma unroll
            for (int i = 0; i < 8; i++)
                #pragma unroll
                for (int j = 0; j < 8; j++) acc[i][j] += a[i] * b[j];
        }
        __syncthreads();
    }

    // Epilogue: add bias, store
    #pragma unroll
    for (int i = 0; i < 8; i++) {
        int row = bm + ty * 8 + i;
        float4 o0, o1;
        int col = bn + tx * 8;
        o0.x = acc[i][0] + bias[col + 0]; o0.y = acc[i][1] + bias[col + 1];
        o0.z = acc[i][2] + bias[col + 2]; o0.w = acc[i][3] + bias[col + 3];
        o1.x = acc[i][4] + bias[col + 4]; o1.y = acc[i][5] + bias[col + 5];
        o1.z = acc[i][6] + bias[col + 6]; o1.w = acc[i][7] + bias[col + 7];
        *(float4*)(C + (size_t)row * N + col)     = o0;
        *(float4*)(C + (size_t)row * N + col + 4) = o1;
    }
}

// ---------------------------------------------------------------------------
// LIF over time axis for q/k/v (vth = 1.0). One thread per (l,b,f) neuron.
// h = v + (x - v) * 0.5 ; spike = (h - vth >= 0) ; v = spike ? 0 : h
// ---------------------------------------------------------------------------
__global__ __launch_bounds__(256) void lif_qkv_kernel()
{
    size_t i = (size_t)blockIdx.x * 256 + threadIdx.x;   // over LB*N3
    float v = 0.f;
    #pragma unroll
    for (int t = 0; t < Tt; t++) {
        float x = g_proj[(size_t)t * LB * N3 + i];
        float h = v + (x - v) * 0.5f;
        bool s = (h - 1.0f) >= 0.f;
        g_spk[(size_t)t * LB * N3 + i] = s ? 1 : 0;
        v = s ? 0.f : h;
    }
}

__global__ __launch_bounds__(256) void zero_attn_kernel()
{
    int i = blockIdx.x * 256 + threadIdx.x;
    g_attn[i] = 0.f;
}

// ---------------------------------------------------------------------------
// attn[t,n,d,e] = sum_l k[t,n,l,d] * v[t,n,l,e]   (binary -> exact counts)
// grid: (lsplit=8, n=64, t=4), block 256 (16x16 threads, 4x4 per thread)
// ---------------------------------------------------------------------------
__global__ __launch_bounds__(256) void kv_attn_kernel()
{
    const int t = blockIdx.z, n = blockIdx.y, ls = blockIdx.x;
    const int b = n >> 3, h = n & 7;
    __shared__ uint8_t ks[32][64];
    __shared__ uint8_t vs[32][64];
    const int tx = threadIdx.x & 15, ty = threadIdx.x >> 4;

    float acc[4][4];
    #pragma unroll
    for (int i = 0; i < 4; i++)
        #pragma unroll
        for (int j = 0; j < 4; j++) acc[i][j] = 0.f;

    for (int l0 = ls * 256; l0 < ls * 256 + 256; l0 += 32) {
        for (int i = threadIdx.x; i < 512; i += 256) {
            int ll = i >> 4, d4 = (i & 15) << 2;
            size_t base = ((size_t)t * LB + (size_t)(l0 + ll) * Bb + b) * N3 + h * 64 + d4;
            *(uchar4*)&ks[ll][d4] = *(const uchar4*)(g_spk + base + 512);   // k
            *(uchar4*)&vs[ll][d4] = *(const uchar4*)(g_spk + base + 1024);  // v
        }
        __syncthreads();
        #pragma unroll 8
        for (int ll = 0; ll < 32; ll++) {
            float ka[4], va[4];
            #pragma unroll
            for (int i = 0; i < 4; i++) ka[i] = (float)ks[ll][ty * 4 + i];
            #pragma unroll
            for (int j = 0; j < 4; j++) va[j] = (float)vs[ll][tx * 4 + j];
            #pragma unroll
            for (int i = 0; i < 4; i++)
                #pragma unroll
                for (int j = 0; j < 4; j++) acc[i][j] += ka[i] * va[j];
        }
        __syncthreads();
    }

    float* ap = g_attn + (size_t)(t * 64 + n) * 64 * 64;
    #pragma unroll
    for (int i = 0; i < 4; i++)
        #pragma unroll
        for (int j = 0; j < 4; j++)
            atomicAdd(ap + (ty * 4 + i) * 64 + tx * 4 + j, acc[i][j]);  // integer sums: exact
}

// ---------------------------------------------------------------------------
// out = (q @ attn) * 0.125, then LIF (vth=0.5) over t, fused.
// grid: (ltile=32 [64 l's each], n=64), block 256: e = tid&63, lr = tid>>6.
// Each thread owns 16 l's (l = lt*64 + li*4 + lr), carries LIF state across t.
// All arithmetic here is exact (integer counts), matching reference bitwise.
// ---------------------------------------------------------------------------
__global__ __launch_bounds__(256) void qattn_lif_kernel()
{
    const int n = blockIdx.y, lt = blockIdx.x;
    const int b = n >> 3, h = n & 7;
    __shared__ float   at[64][64];
    __shared__ uint8_t qs[64][64];
    const int e = threadIdx.x & 63, lr = threadIdx.x >> 6;

    float vmem[16];
    #pragma unroll
    for (int i = 0; i < 16; i++) vmem[i] = 0.f;

    for (int t = 0; t < Tt; t++) {
        __syncthreads();
        // attn tile for (t, n): 64x64 floats
        for (int i = threadIdx.x; i < 4096; i += 256)
            at[i >> 6][i & 63] = g_attn[(size_t)(t * 64 + n) * 4096 + i];
        // q spikes for this l-tile
        for (int i = threadIdx.x; i < 1024; i += 256) {
            int ll = i >> 4, d4 = (i & 15) << 2;
            size_t base = ((size_t)t * LB + (size_t)(lt * 64 + ll) * Bb + b) * N3 + h * 64 + d4;
            *(uchar4*)&qs[ll][d4] = *(const uchar4*)(g_spk + base);
        }
        __syncthreads();

        #pragma unroll
        for (int li = 0; li < 16; li++) {
            int llocal = li * 4 + lr;
            float s = 0.f;
            #pragma unroll
            for (int d = 0; d < 64; d++)
                s += (float)qs[llocal][d] * at[d][e];
            float x = s * 0.125f;                       // exact
            float hh = vmem[li] + (x - vmem[li]) * 0.5f;
            bool sp = (hh - 0.5f) >= 0.f;
            int l = lt * 64 + llocal;
            g_s2[(((size_t)t * Ll + l) * Bb + b) * Ee + h * 64 + e] = sp ? 1.f : 0.f;
            vmem[li] = sp ? 0.f : hh;
        }
    }
}

// ---------------------------------------------------------------------------
extern "C" void kernel_launch(void* const* d_in, const int* in_sizes, int n_in,
                              void* d_out, int out_size)
{
    const float* query = (const float*)d_in[0];   // (T,L,B,E)
    const float* w_in  = (const float*)d_in[1];   // (3E, E)
    const float* b_in  = (const float*)d_in[2];   // (3E)
    const float* w_out = (const float*)d_in[3];   // (E, E)
    const float* b_out = (const float*)d_in[4];   // (E)
    float* out = (float*)d_out;                   // (T,L,B,E)

    void *p_proj = nullptr, *p_s2 = nullptr;
    cudaGetSymbolAddress(&p_proj, g_proj);
    cudaGetSymbolAddress(&p_s2,   g_s2);

    // 1) proj = query @ W_in^T + b_in   (M=65536, N=1536, K=512)
    gemm_bias_kernel<<<dim3(N3 / 128, Mm / 128), 256>>>(
        query, w_in, b_in, (float*)p_proj, Mm, N3, Ee);

    // 2) LIF over T for q,k,v -> binary spikes
    lif_qkv_kernel<<<(LB * N3) / 256, 256>>>();

    // 3) attn = k^T v per (t, head)
    zero_attn_kernel<<<(Tt * 64 * Dd * Dd) / 256, 256>>>();
    kv_attn_kernel<<<dim3(8, 64, Tt), 256>>>();

    // 4) out = q @ attn * 0.125 -> LIF(0.5) -> s2 spikes (as float 0/1)
    qattn_lif_kernel<<<dim3(Ll / 64, 64), 256>>>();

    // 5) final = s2 @ W_out^T + b_out   (M=65536, N=512, K=512)
    gemm_bias_kernel<<<dim3(Ee / 128, Mm / 128), 256>>>(
        (const float*)p_s2, w_out, b_out, out, Mm, Ee, Ee);
}